// round 1
// baseline (speedup 1.0000x reference)
#include <cuda_runtime.h>
#include <math.h>

// ---------------------------------------------------------------------------
// PixelateDegradation:
//   out[b,c] = C_{t[b]} @ x0[b,c] @ C_{t[b]}^T
// where C_t = M_{t-1} ... M_0, M_i = NearestExact(256<-s) @ Bicubic(s<-256),
// s = 256 - i. Each M_i row has <=4 nonzeros (bicubic taps at row src(o)).
// ---------------------------------------------------------------------------

#define TS 20
#define SZ 256
#define NIMG 192           // 64 batch * 3 channels
#define MAXT 12            // max entries per column of M_i (theoretical <=6)

// Static device scratch (allocation-free rule)
__device__ float g_C[TS][SZ][SZ];                       // prefix matrices, C_0 = I
__device__ float g_tmp[(size_t)NIMG * SZ * SZ];         // phase-1 intermediate (50 MB)
__device__ float g_tw[TS][SZ][MAXT];                    // transposed sparse weights
__device__ int   g_trow[TS][SZ][MAXT];                  // transposed sparse row idx
__device__ int   g_tn[TS][SZ];                          // entries per column

// ---------------------------------------------------------------------------
// Kernel 1: build sparse M_i (double precision to match numpy float64 build),
// then build the column-transposed representation (deterministic gather).
// grid = TS blocks, 256 threads.
// ---------------------------------------------------------------------------
__device__ __forceinline__ double cc1d(double x) {
    const double A = -0.75;
    return ((A + 2.0) * x - (A + 3.0)) * x * x + 1.0;
}
__device__ __forceinline__ double cc2d(double x) {
    const double A = -0.75;
    return ((A * x - 5.0 * A) * x + 8.0 * A) * x - 4.0 * A;
}

__global__ void weights_kernel() {
    int i = blockIdx.x;          // step index
    int o = threadIdx.x;         // output row of M_i

    __shared__ float sw[SZ][4];
    __shared__ int   scol[SZ][4];

    double s = (double)(SZ - i);

    // nearest-exact source row
    int src = (int)floor((o + 0.5) * s / 256.0);
    int smax = (SZ - i) - 1;
    if (src > smax) src = smax;
    if (src < 0) src = 0;

    // bicubic taps of B_i at row src
    double x  = (src + 0.5) * 256.0 / s - 0.5;
    double i0 = floor(x);
    double tt = x - i0;
    double w0 = cc2d(tt + 1.0);
    double w1 = cc1d(tt);
    double w2 = cc1d(1.0 - tt);
    double w3 = cc2d(2.0 - tt);
    int ib = (int)i0;

    double ws[4] = {w0, w1, w2, w3};
#pragma unroll
    for (int k = 0; k < 4; k++) {
        int c = ib - 1 + k;
        if (c < 0) c = 0;
        if (c > SZ - 1) c = SZ - 1;
        scol[o][k] = c;
        sw[o][k]   = (float)ws[k];
    }
    __syncthreads();

    // transpose: thread h collects all (r, w) with col(r,k) == h, fixed order
    int h = threadIdx.x;
    int cnt = 0;
    for (int r = 0; r < SZ; r++) {
#pragma unroll
        for (int k = 0; k < 4; k++) {
            if (scol[r][k] == h && cnt < MAXT) {
                g_trow[i][h][cnt] = r;
                g_tw[i][h][cnt]   = sw[r][k];
                cnt++;
            }
        }
    }
    g_tn[i][h] = cnt;
}

// ---------------------------------------------------------------------------
// Kernel 2: prefix products. Block (o, t) computes row o of C_t by applying
// u^T <- u^T M_step for step = t-1 .. 0, starting from e_o.
// Pure gathers via transposed sparse M -> deterministic.
// grid = (256, TS), 256 threads.
// ---------------------------------------------------------------------------
__global__ void chain_kernel() {
    int o = blockIdx.x;
    int t = blockIdx.y;
    int h = threadIdx.x;

    __shared__ float u[SZ];
    u[h] = (h == o) ? 1.0f : 0.0f;
    __syncthreads();

    for (int step = t - 1; step >= 0; --step) {
        int n = g_tn[step][h];
        float acc = 0.0f;
        for (int j = 0; j < n; j++)
            acc += g_tw[step][h][j] * u[g_trow[step][h][j]];
        __syncthreads();
        u[h] = acc;
        __syncthreads();
    }
    g_C[t][o][h] = u[h];
}

// ---------------------------------------------------------------------------
// Main GEMMs: 256x256x256 fp32 per image, tile 128x128x16, 8x8 per thread.
// phase1: tmp = C @ X        (A = C,    B = X,  NN)
// phase2: out = tmp @ C^T    (A = tmp,  B = C,  NT: B[n][k])
// grid = (2, 2, NIMG), 256 threads.
// ---------------------------------------------------------------------------
#define BM 128
#define BN 128
#define BK 16
#define SPAD 4

struct GemmSmem {
    __align__(16) float As[BK][BM + SPAD];
    __align__(16) float Bs[BK][BN + SPAD];
};

template <bool B_TRANS>
__device__ __forceinline__ void gemm_body(const float* __restrict__ A,
                                          const float* __restrict__ B,
                                          float* __restrict__ Cout) {
    __shared__ GemmSmem sm;

    int tid = threadIdx.x;
    int tx = tid & 15;
    int ty = tid >> 4;
    int rowBase = blockIdx.y * BM;
    int colBase = blockIdx.x * BN;

    float acc[8][8];
#pragma unroll
    for (int i = 0; i < 8; i++)
#pragma unroll
        for (int j = 0; j < 8; j++) acc[i][j] = 0.0f;

    for (int kt = 0; kt < SZ; kt += BK) {
        // ---- load A tile (128 x 16), store k-major transposed ----
#pragma unroll
        for (int it = 0; it < 2; it++) {
            int idx = tid + it * 256;          // 0..511
            int r   = idx >> 2;                // 0..127
            int kc  = (idx & 3) << 2;          // 0,4,8,12
            float4 v = *reinterpret_cast<const float4*>(
                A + (size_t)(rowBase + r) * SZ + kt + kc);
            sm.As[kc + 0][r] = v.x;
            sm.As[kc + 1][r] = v.y;
            sm.As[kc + 2][r] = v.z;
            sm.As[kc + 3][r] = v.w;
        }
        // ---- load B tile (16 x 128) ----
        if (!B_TRANS) {
#pragma unroll
            for (int it = 0; it < 2; it++) {
                int idx = tid + it * 256;
                int kr  = idx >> 5;            // 0..15
                int nc  = (idx & 31) << 2;     // 0..124
                float4 v = *reinterpret_cast<const float4*>(
                    B + (size_t)(kt + kr) * SZ + colBase + nc);
                *reinterpret_cast<float4*>(&sm.Bs[kr][nc]) = v;
            }
        } else {
            // B stored as [n][k] (row-major, k contiguous): transpose on load
#pragma unroll
            for (int it = 0; it < 2; it++) {
                int idx = tid + it * 256;
                int n   = idx >> 2;            // 0..127
                int kc  = (idx & 3) << 2;      // 0,4,8,12
                float4 v = *reinterpret_cast<const float4*>(
                    B + (size_t)(colBase + n) * SZ + kt + kc);
                sm.Bs[kc + 0][n] = v.x;
                sm.Bs[kc + 1][n] = v.y;
                sm.Bs[kc + 2][n] = v.z;
                sm.Bs[kc + 3][n] = v.w;
            }
        }
        __syncthreads();

#pragma unroll
        for (int k = 0; k < BK; k++) {
            float ar[8], br[8];
            *reinterpret_cast<float4*>(&ar[0]) =
                *reinterpret_cast<const float4*>(&sm.As[k][ty * 4]);
            *reinterpret_cast<float4*>(&ar[4]) =
                *reinterpret_cast<const float4*>(&sm.As[k][64 + ty * 4]);
            *reinterpret_cast<float4*>(&br[0]) =
                *reinterpret_cast<const float4*>(&sm.Bs[k][tx * 4]);
            *reinterpret_cast<float4*>(&br[4]) =
                *reinterpret_cast<const float4*>(&sm.Bs[k][64 + tx * 4]);
#pragma unroll
            for (int i = 0; i < 8; i++)
#pragma unroll
                for (int j = 0; j < 8; j++) acc[i][j] += ar[i] * br[j];
        }
        __syncthreads();
    }

    // ---- epilogue ----
#pragma unroll
    for (int i = 0; i < 8; i++) {
        int m = rowBase + ((i < 4) ? (ty * 4 + i) : (64 + ty * 4 + i - 4));
        float4 v0 = make_float4(acc[i][0], acc[i][1], acc[i][2], acc[i][3]);
        float4 v1 = make_float4(acc[i][4], acc[i][5], acc[i][6], acc[i][7]);
        *reinterpret_cast<float4*>(Cout + (size_t)m * SZ + colBase + tx * 4) = v0;
        *reinterpret_cast<float4*>(Cout + (size_t)m * SZ + colBase + 64 + tx * 4) = v1;
    }
}

__global__ void __launch_bounds__(256)
phase1_kernel(const float* __restrict__ x0, const int* __restrict__ t) {
    int img = blockIdx.z;
    int b   = img / 3;
    int tb  = t[b];
    const float* A = &g_C[tb][0][0];
    const float* B = x0 + (size_t)img * SZ * SZ;
    float* Cout    = g_tmp + (size_t)img * SZ * SZ;
    gemm_body<false>(A, B, Cout);
}

__global__ void __launch_bounds__(256)
phase2_kernel(float* __restrict__ out, const int* __restrict__ t) {
    int img = blockIdx.z;
    int b   = img / 3;
    int tb  = t[b];
    const float* A = g_tmp + (size_t)img * SZ * SZ;
    const float* B = &g_C[tb][0][0];   // used as B[n][k] -> out = A @ C^T
    float* Cout    = out + (size_t)img * SZ * SZ;
    gemm_body<true>(A, B, Cout);
}

// ---------------------------------------------------------------------------
extern "C" void kernel_launch(void* const* d_in, const int* in_sizes, int n_in,
                              void* d_out, int out_size) {
    const float* x0 = (const float*)d_in[0];
    const int*   t  = (const int*)d_in[1];
    float* out      = (float*)d_out;

    weights_kernel<<<TS, 256>>>();
    chain_kernel<<<dim3(SZ, TS), 256>>>();
    phase1_kernel<<<dim3(2, 2, NIMG), 256>>>(x0, t);
    phase2_kernel<<<dim3(2, 2, NIMG), 256>>>(out, t);
}

// round 3
// speedup vs baseline: 1.5811x; 1.5811x over previous
#include <cuda_runtime.h>
#include <cuda_fp16.h>
#include <math.h>
#include <stdint.h>

// ===========================================================================
// PixelateDegradation:  out[b,c] = C_{t[b]} @ x0[b,c] @ C_{t[b]}^T
// Tensor-core path via mma.sync (sm_103 base target; tcgen05 unavailable).
// fp16 split precision: D += Ah Bh + Ah Bl + Al Bh  (fp32 accumulate).
// ===========================================================================

#define TS 20
#define SZ 256
#define NIMG 192
#define MAXT 12

__device__ float g_C[TS][SZ][SZ];
__device__ float g_tmp[(size_t)NIMG * SZ * SZ];
__device__ float g_tw[TS][SZ][MAXT];
__device__ int   g_trow[TS][SZ][MAXT];
__device__ int   g_tn[TS][SZ];

// ---------------------------------------------------------------------------
// Setup kernels (unchanged from passing round-1 baseline)
// ---------------------------------------------------------------------------
__device__ __forceinline__ double cc1d(double x) {
    const double A = -0.75;
    return ((A + 2.0) * x - (A + 3.0)) * x * x + 1.0;
}
__device__ __forceinline__ double cc2d(double x) {
    const double A = -0.75;
    return ((A * x - 5.0 * A) * x + 8.0 * A) * x - 4.0 * A;
}

__global__ void weights_kernel() {
    int i = blockIdx.x;
    int o = threadIdx.x;
    __shared__ float sw[SZ][4];
    __shared__ int   scol[SZ][4];

    double s = (double)(SZ - i);
    int src = (int)floor((o + 0.5) * s / 256.0);
    int smax = (SZ - i) - 1;
    if (src > smax) src = smax;
    if (src < 0) src = 0;

    double x  = (src + 0.5) * 256.0 / s - 0.5;
    double i0 = floor(x);
    double tt = x - i0;
    double ws[4] = {cc2d(tt + 1.0), cc1d(tt), cc1d(1.0 - tt), cc2d(2.0 - tt)};
    int ib = (int)i0;
#pragma unroll
    for (int k = 0; k < 4; k++) {
        int c = ib - 1 + k;
        if (c < 0) c = 0;
        if (c > SZ - 1) c = SZ - 1;
        scol[o][k] = c;
        sw[o][k]   = (float)ws[k];
    }
    __syncthreads();

    int h = threadIdx.x;
    int cnt = 0;
    for (int r = 0; r < SZ; r++) {
#pragma unroll
        for (int k = 0; k < 4; k++) {
            if (scol[r][k] == h && cnt < MAXT) {
                g_trow[i][h][cnt] = r;
                g_tw[i][h][cnt]   = sw[r][k];
                cnt++;
            }
        }
    }
    g_tn[i][h] = cnt;
}

__global__ void chain_kernel() {
    int o = blockIdx.x;
    int t = blockIdx.y;
    int h = threadIdx.x;

    __shared__ float u[SZ];
    u[h] = (h == o) ? 1.0f : 0.0f;
    __syncthreads();

    for (int step = t - 1; step >= 0; --step) {
        int n = g_tn[step][h];
        float acc = 0.0f;
        for (int j = 0; j < n; j++)
            acc += g_tw[step][h][j] * u[g_trow[step][h][j]];
        __syncthreads();
        u[h] = acc;
        __syncthreads();
    }
    g_C[t][o][h] = u[h];
}

// ---------------------------------------------------------------------------
// mma.sync tensor-core GEMM, fp16 split precision
// ---------------------------------------------------------------------------
// smem (dynamic, 40960 B): hi/lo fp16 tiles, 80-byte row pitch
//   Ah [0,10240)  Al [10240,20480)  Bh [20480,30720)  Bl [30720,40960)
// Row r of a tile holds 32 fp16 k-values at r*80 (64B used, 16B pad).
// (5r+s) mod 8 covers all 16B phase-groups -> conflict-free ldmatrix.

static constexpr int SMEM_BYTES = 40960;
static constexpr uint32_t OFF_AL = 10240;
static constexpr uint32_t OFF_BH = 20480;

__device__ __forceinline__ uint32_t smem_to_u32(const void* p) {
    uint32_t a;
    asm("{ .reg .u64 t; cvta.to.shared.u64 t, %1; cvt.u32.u64 %0, t; }"
        : "=r"(a) : "l"(p));
    return a;
}

__device__ __forceinline__ void ldsm_x4(uint32_t r[4], uint32_t addr) {
    asm volatile("ldmatrix.sync.aligned.m8n8.x4.shared.b16 {%0,%1,%2,%3}, [%4];"
                 : "=r"(r[0]), "=r"(r[1]), "=r"(r[2]), "=r"(r[3]) : "r"(addr));
}

__device__ __forceinline__ void mma16816(float d[4], const uint32_t a[4],
                                         const uint32_t b[2]) {
    asm volatile(
        "mma.sync.aligned.m16n8k16.row.col.f32.f16.f16.f32 "
        "{%0,%1,%2,%3}, {%4,%5,%6,%7}, {%8,%9}, {%0,%1,%2,%3};"
        : "+f"(d[0]), "+f"(d[1]), "+f"(d[2]), "+f"(d[3])
        : "r"(a[0]), "r"(a[1]), "r"(a[2]), "r"(a[3]), "r"(b[0]), "r"(b[1]));
}

#define STS128(r0, r1, r2, r3, addr) \
    asm volatile("st.shared.v4.b32 [%0], {%1, %2, %3, %4};" \
        :: "r"(addr), "r"(r0), "r"(r1), "r"(r2), "r"(r3) : "memory")

__device__ __forceinline__ void split_pack8(const float v[8], uint32_t hi[4],
                                            uint32_t lo[4]) {
#pragma unroll
    for (int i = 0; i < 4; i++) {
        float a = v[2 * i], b = v[2 * i + 1];
        __half ha = __float2half_rn(a), hb = __float2half_rn(b);
        __half la = __float2half_rn(a - __half2float(ha));
        __half lb = __float2half_rn(b - __half2float(hb));
        __half2 h = __halves2half2(ha, hb);
        __half2 l = __halves2half2(la, lb);
        hi[i] = *reinterpret_cast<const uint32_t*>(&h);
        lo[i] = *reinterpret_cast<const uint32_t*>(&l);
    }
}

// stage 8 consecutive fp32 -> hi/lo fp16 at tile row `row`, 16B chunk s.
__device__ __forceinline__ void stage8(uint32_t hiBase, int row, int s,
                                       const float* __restrict__ src8) {
    const float4* p4 = reinterpret_cast<const float4*>(src8);
    float4 a = p4[0], b = p4[1];
    float v[8] = {a.x, a.y, a.z, a.w, b.x, b.y, b.z, b.w};
    uint32_t hi[4], lo[4];
    split_pack8(v, hi, lo);
    uint32_t addr = hiBase + (uint32_t)(row * 80 + s * 16);
    STS128(hi[0], hi[1], hi[2], hi[3], addr);
    STS128(lo[0], lo[1], lo[2], lo[3], addr + OFF_AL);
}

// D[mb:mb+128, nb:nb+128] = A[128,256] @ op(B); BT ? B[n][k]=Bg[k][n] : Bg rows
template <bool BT>
__device__ __forceinline__ void gemm_device(const float* __restrict__ Ag,
                                            const float* __restrict__ Bg,
                                            float* __restrict__ Dg) {
    extern __shared__ char smem[];
    uint32_t sb = smem_to_u32(smem);

    const int tid   = threadIdx.x;
    const int lane  = tid & 31;
    const int wid   = tid >> 5;
    const int warpm = wid & 3;
    const int warpn = wid >> 2;
    const int mb    = blockIdx.y * 128;
    const int nb    = blockIdx.x * 128;

    float acc[2][8][4];
#pragma unroll
    for (int i = 0; i < 2; i++)
#pragma unroll
        for (int j = 0; j < 8; j++)
#pragma unroll
            for (int q = 0; q < 4; q++) acc[i][j][q] = 0.0f;

    // lane-invariant ldmatrix offsets
    const uint32_t aoff = sb +
        (uint32_t)((warpm * 32 + (lane & 15)) * 80 + ((lane & 16) ? 16 : 0));
    const uint32_t boff = sb + OFF_BH +
        (uint32_t)((warpn * 64 + (lane & 7) + ((lane & 16) ? 8 : 0)) * 80 +
                   ((lane & 8) ? 16 : 0));

#pragma unroll 1
    for (int c = 0; c < 8; c++) {
        const int kc = c * 32;

        // ---- stage A (128 rows x 32 k) ----
        {
            int r = tid >> 1, half = tid & 1;
            const float* src = Ag + (size_t)(mb + r) * SZ + kc + half * 16;
            stage8(sb, r, half * 2, src);
            stage8(sb, r, half * 2 + 1, src + 8);
        }
        // ---- stage B (128 n-rows x 32 k) ----
        if (!BT) {
            int r = tid >> 1, half = tid & 1;
            const float* src = Bg + (size_t)(nb + r) * SZ + kc + half * 16;
            stage8(sb + OFF_BH, r, half * 2, src);
            stage8(sb + OFF_BH, r, half * 2 + 1, src + 8);
        } else {
#pragma unroll
            for (int rep = 0; rep < 2; rep++) {
                int it = wid + rep * 8;            // 16 tasks
                int j0 = (it & 3) * 8;             // k group
                int n0 = (it >> 2) * 32;           // n group
                const float* xp = Bg + (size_t)(kc + j0) * SZ + nb + n0 + lane;
                float v[8];
#pragma unroll
                for (int j = 0; j < 8; j++) v[j] = xp[(size_t)j * SZ];
                uint32_t hi[4], lo[4];
                split_pack8(v, hi, lo);
                uint32_t addr = sb + OFF_BH +
                    (uint32_t)((n0 + lane) * 80 + (j0 >> 3) * 16);
                STS128(hi[0], hi[1], hi[2], hi[3], addr);
                STS128(lo[0], lo[1], lo[2], lo[3], addr + OFF_AL);
            }
        }
        __syncthreads();

        // ---- compute ----
#pragma unroll
        for (int K16 = 0; K16 < 2; K16++) {
            uint32_t aH[2][4], aL[2][4];
#pragma unroll
            for (int mt = 0; mt < 2; mt++) {
                uint32_t a = aoff + (uint32_t)(mt * 16 * 80 + K16 * 32);
                ldsm_x4(aH[mt], a);
                ldsm_x4(aL[mt], a + OFF_AL);
            }
#pragma unroll
            for (int g = 0; g < 4; g++) {
                uint32_t bH[4], bL[4];
                uint32_t b = boff + (uint32_t)(g * 16 * 80 + K16 * 32);
                ldsm_x4(bH, b);
                ldsm_x4(bL, b + OFF_AL);
#pragma unroll
                for (int mt = 0; mt < 2; mt++) {
                    mma16816(acc[mt][2 * g],     aH[mt], bH);
                    mma16816(acc[mt][2 * g + 1], aH[mt], bH + 2);
                    mma16816(acc[mt][2 * g],     aH[mt], bL);
                    mma16816(acc[mt][2 * g + 1], aH[mt], bL + 2);
                    mma16816(acc[mt][2 * g],     aL[mt], bH);
                    mma16816(acc[mt][2 * g + 1], aL[mt], bH + 2);
                }
            }
        }
        __syncthreads();
    }

    // ---- epilogue ----
    const int row = mb + warpm * 32 + (lane >> 2);
    const int col = nb + warpn * 64 + (lane & 3) * 2;
#pragma unroll
    for (int mt = 0; mt < 2; mt++) {
#pragma unroll
        for (int nt = 0; nt < 8; nt++) {
            float* p0 = Dg + (size_t)(row + mt * 16) * SZ + col + nt * 8;
            float* p1 = Dg + (size_t)(row + mt * 16 + 8) * SZ + col + nt * 8;
            *reinterpret_cast<float2*>(p0) =
                make_float2(acc[mt][nt][0], acc[mt][nt][1]);
            *reinterpret_cast<float2*>(p1) =
                make_float2(acc[mt][nt][2], acc[mt][nt][3]);
        }
    }
}

__global__ void __launch_bounds__(256, 2)
phase1_kernel(const float* __restrict__ x0, const int* __restrict__ t) {
    int img = blockIdx.z;
    int tb  = __ldg(&t[img / 3]);
    gemm_device<true>(&g_C[tb][0][0], x0 + (size_t)img * SZ * SZ,
                      g_tmp + (size_t)img * SZ * SZ);
}

__global__ void __launch_bounds__(256, 2)
phase2_kernel(float* __restrict__ out, const int* __restrict__ t) {
    int img = blockIdx.z;
    int tb  = __ldg(&t[img / 3]);
    gemm_device<false>(g_tmp + (size_t)img * SZ * SZ, &g_C[tb][0][0],
                       out + (size_t)img * SZ * SZ);
}

// ---------------------------------------------------------------------------
extern "C" void kernel_launch(void* const* d_in, const int* in_sizes, int n_in,
                              void* d_out, int out_size) {
    const float* x0 = (const float*)d_in[0];
    const int*   t  = (const int*)d_in[1];
    float* out      = (float*)d_out;

    weights_kernel<<<TS, 256>>>();
    chain_kernel<<<dim3(SZ, TS), 256>>>();

    cudaFuncSetAttribute(phase1_kernel,
                         cudaFuncAttributeMaxDynamicSharedMemorySize, SMEM_BYTES);
    cudaFuncSetAttribute(phase2_kernel,
                         cudaFuncAttributeMaxDynamicSharedMemorySize, SMEM_BYTES);
    phase1_kernel<<<dim3(2, 2, NIMG), 256, SMEM_BYTES>>>(x0, t);
    phase2_kernel<<<dim3(2, 2, NIMG), 256, SMEM_BYTES>>>(out, t);
}